// round 1
// baseline (speedup 1.0000x reference)
#include <cuda_runtime.h>
#include <cuda_bf16.h>
#include <math.h>

#define NN 20000
#define EE 320000
#define GG 64

// ---------------- device scratch (no allocations allowed) ----------------
__device__ float g_mean[NN * 128];
__device__ float g_h1[NN * 128];
__device__ float g_h2[NN * 256];
__device__ float g_q[NN * 256];
__device__ float g_k[NN * 256];
__device__ float g_v[NN * 256];
__device__ float g_skip[NN * 256];
__device__ float g_h3[NN * 256];
__device__ float g_h4[NN * 256];
__device__ float g_p1[NN * 512];
__device__ float g_p2[NN * 128];
__device__ int g_deg[NN];
__device__ int g_fill[NN];
__device__ int g_rowptr[NN + 1];
__device__ int g_csrc[EE];

// ---------------- CSR build ----------------
__global__ void k_zero(float* out) {
    int i = blockIdx.x * blockDim.x + threadIdx.x;
    if (i < NN) { g_deg[i] = 0; g_fill[i] = 0; }
    if (i < GG * 128) out[i] = 0.0f;
}

__global__ void k_hist(const int* __restrict__ dst) {
    int e = blockIdx.x * blockDim.x + threadIdx.x;
    if (e < EE) atomicAdd(&g_deg[dst[e]], 1);
}

__global__ void k_scan() {
    __shared__ int sh[1024];
    __shared__ int carry;
    int tid = threadIdx.x;
    if (tid == 0) carry = 0;
    __syncthreads();
    for (int base = 0; base < NN; base += 1024) {
        int i = base + tid;
        int val = (i < NN) ? g_deg[i] : 0;
        sh[tid] = val;
        __syncthreads();
        for (int off = 1; off < 1024; off <<= 1) {
            int t = (tid >= off) ? sh[tid - off] : 0;
            __syncthreads();
            sh[tid] += t;
            __syncthreads();
        }
        if (i < NN) g_rowptr[i] = carry + sh[tid] - val;   // exclusive
        int tot = sh[1023];
        __syncthreads();
        if (tid == 0) carry += tot;
        __syncthreads();
    }
    if (tid == 0) g_rowptr[NN] = carry;
}

__global__ void k_scatter(const int* __restrict__ src, const int* __restrict__ dst) {
    int e = blockIdx.x * blockDim.x + threadIdx.x;
    if (e >= EE) return;
    int d = dst[e];
    int pos = atomicAdd(&g_fill[d], 1);
    g_csrc[g_rowptr[d] + pos] = src[e];
}

// ---------------- SAGE mean aggregation (warp per node, 128-dim) ----------------
__global__ void k_sage_agg(const float* __restrict__ x, float* __restrict__ mean) {
    int w = (blockIdx.x * blockDim.x + threadIdx.x) >> 5;
    int lane = threadIdx.x & 31;
    if (w >= NN) return;
    int beg = g_rowptr[w], end = g_rowptr[w + 1];
    float4 acc = make_float4(0.f, 0.f, 0.f, 0.f);
    for (int e = beg; e < end; e++) {
        int s = g_csrc[e];
        float4 xv = *(const float4*)(x + (size_t)s * 128 + lane * 4);
        acc.x += xv.x; acc.y += xv.y; acc.z += xv.z; acc.w += xv.w;
    }
    float inv = 1.0f / fmaxf((float)(end - beg), 1.0f);
    acc.x *= inv; acc.y *= inv; acc.z *= inv; acc.w *= inv;
    *(float4*)(mean + (size_t)w * 128 + lane * 4) = acc;
}

// ---------------- tiled fp32 GEMM, dual-A (C = act(A1@W1 + A2@W2 + bias)) ------
// BM=128, BN=128, BK=16, 256 threads, 8x8 per thread
#define BM 128
#define BN 128
#define BKK 16

__global__ __launch_bounds__(256, 2)
void gemm_dual(const float* __restrict__ A1, int K1, const float* __restrict__ W1,
               const float* __restrict__ A2, int K2, const float* __restrict__ W2,
               const float* __restrict__ bias, float* __restrict__ C,
               int M, int Nc, int act) {
    __shared__ float As[BKK][BM];
    __shared__ float Bs[BKK][BN];
    int bm = blockIdx.y * BM;
    int bn = blockIdx.x * BN;
    int tid = threadIdx.x;
    int tm = (tid / 16) * 8;
    int tn = (tid % 16) * 8;
    float acc[8][8];
#pragma unroll
    for (int i = 0; i < 8; i++)
#pragma unroll
        for (int j = 0; j < 8; j++) acc[i][j] = 0.f;

    for (int pass = 0; pass < 2; ++pass) {
        const float* A = pass ? A2 : A1;
        const float* W = pass ? W2 : W1;
        int K = pass ? K2 : K1;
        if (A == nullptr || K == 0) continue;
        for (int k0 = 0; k0 < K; k0 += BKK) {
            // A tile: 128 rows x 16 cols
#pragma unroll
            for (int l = 0; l < 2; ++l) {
                int idx = tid + l * 256;        // 0..511
                int row = idx >> 2;             // 0..127
                int c4 = (idx & 3) << 2;        // 0,4,8,12
                int grow = bm + row;
                float4 av = make_float4(0.f, 0.f, 0.f, 0.f);
                if (grow < M) av = *(const float4*)(A + (size_t)grow * K + k0 + c4);
                As[c4 + 0][row] = av.x; As[c4 + 1][row] = av.y;
                As[c4 + 2][row] = av.z; As[c4 + 3][row] = av.w;
            }
            // W tile: 16 rows x 128 cols
#pragma unroll
            for (int l = 0; l < 2; ++l) {
                int idx = tid + l * 256;
                int row = idx >> 5;             // 0..15
                int c4 = (idx & 31) << 2;       // 0..124
                float4 wv = *(const float4*)(W + (size_t)(k0 + row) * Nc + bn + c4);
                *(float4*)&Bs[row][c4] = wv;
            }
            __syncthreads();
#pragma unroll
            for (int kk = 0; kk < BKK; ++kk) {
                float ra[8], rb[8];
#pragma unroll
                for (int i = 0; i < 8; i++) ra[i] = As[kk][tm + i];
#pragma unroll
                for (int j = 0; j < 8; j++) rb[j] = Bs[kk][tn + j];
#pragma unroll
                for (int i = 0; i < 8; i++)
#pragma unroll
                    for (int j = 0; j < 8; j++) acc[i][j] += ra[i] * rb[j];
            }
            __syncthreads();
        }
    }
    // epilogue
#pragma unroll
    for (int i = 0; i < 8; i++) {
        int grow = bm + tm + i;
        if (grow < M) {
#pragma unroll
            for (int j = 0; j < 8; j++) {
                int gcol = bn + tn + j;
                float v = acc[i][j] + bias[gcol];
                if (act == 1) v = fmaxf(v, 0.f);
                else if (act == 2) v = 1.0f / (1.0f + __expf(-v));
                C[(size_t)grow * Nc + gcol] = v;
            }
        }
    }
}

// ---------------- TransformerConv attention: warp per (node, head) -----------
// online softmax over CSR in-edges; out = relu(skip + softmax(q.k/sqrt(32)) @ v)
__global__ void k_attn(const float* __restrict__ q, const float* __restrict__ k,
                       const float* __restrict__ v, const float* __restrict__ skip,
                       float* __restrict__ out) {
    int w = (blockIdx.x * blockDim.x + threadIdx.x) >> 5;
    if (w >= NN * 8) return;
    int lane = threadIdx.x & 31;
    int node = w >> 3, head = w & 7;
    int col = head * 32 + lane;
    float qv = q[(size_t)node * 256 + col];
    int beg = g_rowptr[node], end = g_rowptr[node + 1];
    float m = -3.0e38f, s = 0.f, acc = 0.f;
    for (int e = beg; e < end; e++) {
        int sn = g_csrc[e];
        float d = qv * k[(size_t)sn * 256 + col];
#pragma unroll
        for (int off = 16; off; off >>= 1) d += __shfl_xor_sync(0xffffffffu, d, off);
        d *= 0.17677669529663687f;  // 1/sqrt(32)
        float mn = fmaxf(m, d);
        float sc = __expf(m - mn);  // exp(-inf)=0 on first edge
        float p  = __expf(d - mn);
        s = s * sc + p;
        acc = acc * sc + p * v[(size_t)sn * 256 + col];
        m = mn;
    }
    float r = (end > beg) ? (acc / s) : 0.f;
    size_t o = (size_t)node * 256 + col;
    out[o] = fmaxf(skip[o] + r, 0.f);
}

// ---------------- global max pool (sigmoid output > 0 -> int atomicMax ok) ----
__global__ void k_pool(const int* __restrict__ batch, float* __restrict__ out) {
    int i = blockIdx.x * blockDim.x + threadIdx.x;
    if (i >= NN * 128) return;
    int node = i >> 7, d = i & 127;
    float val = g_p2[i];
    atomicMax((int*)&out[(size_t)batch[node] * 128 + d], __float_as_int(val));
}

// ---------------- host orchestration ----------------
static void run_gemm(const float* A1, int K1, const float* W1,
                     const float* A2, int K2, const float* W2,
                     const float* bias, float* C, int M, int Nc, int act) {
    dim3 grid(Nc / BN, (M + BM - 1) / BM);
    gemm_dual<<<grid, 256>>>(A1, K1, W1, A2, K2, W2, bias, C, M, Nc, act);
}

extern "C" void kernel_launch(void* const* d_in, const int* in_sizes, int n_in,
                              void* d_out, int out_size) {
    const float* x      = (const float*)d_in[0];
    const int*   ei     = (const int*)d_in[1];
    const int*   batch  = (const int*)d_in[2];
    const float* s1_wl  = (const float*)d_in[3];
    const float* s1_bl  = (const float*)d_in[4];
    const float* s1_wr  = (const float*)d_in[5];
    const float* s2_wl  = (const float*)d_in[6];
    const float* s2_bl  = (const float*)d_in[7];
    const float* s2_wr  = (const float*)d_in[8];
    const float* t1_wq  = (const float*)d_in[9];
    const float* t1_bq  = (const float*)d_in[10];
    const float* t1_wk  = (const float*)d_in[11];
    const float* t1_bk  = (const float*)d_in[12];
    const float* t1_wv  = (const float*)d_in[13];
    const float* t1_bv  = (const float*)d_in[14];
    const float* t1_ws  = (const float*)d_in[15];
    const float* t1_bs  = (const float*)d_in[16];
    const float* t2_wq  = (const float*)d_in[17];
    const float* t2_bq  = (const float*)d_in[18];
    const float* t2_wk  = (const float*)d_in[19];
    const float* t2_bk  = (const float*)d_in[20];
    const float* t2_wv  = (const float*)d_in[21];
    const float* t2_bv  = (const float*)d_in[22];
    const float* t2_ws  = (const float*)d_in[23];
    const float* t2_bs  = (const float*)d_in[24];
    const float* p1_w   = (const float*)d_in[25];
    const float* p1_b   = (const float*)d_in[26];
    const float* p2_w   = (const float*)d_in[27];
    const float* p2_b   = (const float*)d_in[28];

    const int* e_src = ei;        // edge_index[0]
    const int* e_dst = ei + EE;   // edge_index[1]

    float *d_mean, *d_h1, *d_h2, *d_q, *d_k, *d_v, *d_skip, *d_h3, *d_h4, *d_p1, *d_p2;
    cudaGetSymbolAddress((void**)&d_mean, g_mean);
    cudaGetSymbolAddress((void**)&d_h1, g_h1);
    cudaGetSymbolAddress((void**)&d_h2, g_h2);
    cudaGetSymbolAddress((void**)&d_q, g_q);
    cudaGetSymbolAddress((void**)&d_k, g_k);
    cudaGetSymbolAddress((void**)&d_v, g_v);
    cudaGetSymbolAddress((void**)&d_skip, g_skip);
    cudaGetSymbolAddress((void**)&d_h3, g_h3);
    cudaGetSymbolAddress((void**)&d_h4, g_h4);
    cudaGetSymbolAddress((void**)&d_p1, g_p1);
    cudaGetSymbolAddress((void**)&d_p2, g_p2);

    // CSR build (edge_index identical every call -> deterministic)
    k_zero<<<(NN + 255) / 256, 256>>>((float*)d_out);
    k_hist<<<(EE + 255) / 256, 256>>>(e_dst);
    k_scan<<<1, 1024>>>();
    k_scatter<<<(EE + 255) / 256, 256>>>(e_src, e_dst);

    // SAGE 1: h1 = relu(mean(x) @ wl + x @ wr + bl)   [N,128]
    k_sage_agg<<<(NN * 32 + 255) / 256, 256>>>(x, d_mean);
    run_gemm(d_mean, 128, s1_wl, x, 128, s1_wr, s1_bl, d_h1, NN, 128, 1);

    // SAGE 2: h2 = relu(mean(h1) @ wl + h1 @ wr + bl) [N,256]
    k_sage_agg<<<(NN * 32 + 255) / 256, 256>>>(d_h1, d_mean);
    run_gemm(d_mean, 128, s2_wl, d_h1, 128, s2_wr, s2_bl, d_h2, NN, 256, 1);

    // TransformerConv 1
    run_gemm(d_h2, 256, t1_wq, nullptr, 0, nullptr, t1_bq, d_q, NN, 256, 0);
    run_gemm(d_h2, 256, t1_wk, nullptr, 0, nullptr, t1_bk, d_k, NN, 256, 0);
    run_gemm(d_h2, 256, t1_wv, nullptr, 0, nullptr, t1_bv, d_v, NN, 256, 0);
    run_gemm(d_h2, 256, t1_ws, nullptr, 0, nullptr, t1_bs, d_skip, NN, 256, 0);
    k_attn<<<(NN * 8 * 32 + 255) / 256, 256>>>(d_q, d_k, d_v, d_skip, d_h3);

    // TransformerConv 2
    run_gemm(d_h3, 256, t2_wq, nullptr, 0, nullptr, t2_bq, d_q, NN, 256, 0);
    run_gemm(d_h3, 256, t2_wk, nullptr, 0, nullptr, t2_bk, d_k, NN, 256, 0);
    run_gemm(d_h3, 256, t2_wv, nullptr, 0, nullptr, t2_bv, d_v, NN, 256, 0);
    run_gemm(d_h3, 256, t2_ws, nullptr, 0, nullptr, t2_bs, d_skip, NN, 256, 0);
    k_attn<<<(NN * 8 * 32 + 255) / 256, 256>>>(d_q, d_k, d_v, d_skip, d_h4);

    // proj MLP: relu(h4 @ p1 + b1) -> sigmoid(@ p2 + b2)
    run_gemm(d_h4, 256, p1_w, nullptr, 0, nullptr, p1_b, d_p1, NN, 512, 1);
    run_gemm(d_p1, 512, p2_w, nullptr, 0, nullptr, p2_b, d_p2, NN, 128, 2);

    // global max pool per graph
    k_pool<<<(NN * 128 + 255) / 256, 256>>>(batch, (float*)d_out);
}

// round 3
// speedup vs baseline: 1.9787x; 1.9787x over previous
#include <cuda_runtime.h>
#include <cuda_bf16.h>
#include <math.h>
#include <stdint.h>

#define NN 20000
#define EE 320000
#define GG 64
#define MPAD 20096          // 157 * 128
#define NTILES 157

// ---------------- device scratch (no allocations allowed) ----------------
__device__ float g_mean[NN * 128];
__device__ float g_h1[NN * 128];
__device__ float g_h2[NN * 256];
__device__ float g_h3[NN * 256];
__device__ float g_h4[NN * 256];
__device__ float g_qkvs[(size_t)NN * 1024];
__device__ float g_p1[NN * 512];
__device__ float g_p2[NN * 128];
__device__ int g_deg[NN];
__device__ int g_fill[NN];
__device__ int g_rowptr[NN + 1];
__device__ int g_csrc[EE];

// bf16x3 operand images
__device__ __nv_bfloat16 g_Abf[(size_t)MPAD * 1536];     // [MPAD][3K], K<=512
__device__ __nv_bfloat16 g_Wbf[2457600];                 // all weight images

// weight image offsets (elements), layout [Nc][3K]
#define OFF_S1   0          // 128 x 768
#define OFF_S2   98304      // 256 x 768
#define OFF_T1   294912     // 1024 x 768 (q|k|v|s rows)
#define OFF_T2   1081344    // 1024 x 768
#define OFF_P1   1867776    // 512 x 768
#define OFF_P2   2260992    // 128 x 1536

__device__ __forceinline__ uint32_t smem_u32(const void* p) {
    uint32_t a;
    asm("{ .reg .u64 t; cvta.to.shared.u64 t, %1; cvt.u32.u64 %0, t; }" : "=r"(a) : "l"(p));
    return a;
}

// ---------------- CSR build ----------------
__global__ void k_zero(float* out) {
    int i = blockIdx.x * blockDim.x + threadIdx.x;
    if (i < NN) { g_deg[i] = 0; g_fill[i] = 0; }
    if (i < GG * 128) out[i] = 0.0f;
}
__global__ void k_hist(const int* __restrict__ dst) {
    int e = blockIdx.x * blockDim.x + threadIdx.x;
    if (e < EE) atomicAdd(&g_deg[dst[e]], 1);
}
__global__ void k_scan() {
    __shared__ int sh[1024];
    __shared__ int carry;
    int tid = threadIdx.x;
    if (tid == 0) carry = 0;
    __syncthreads();
    for (int base = 0; base < NN; base += 1024) {
        int i = base + tid;
        int val = (i < NN) ? g_deg[i] : 0;
        sh[tid] = val;
        __syncthreads();
        for (int off = 1; off < 1024; off <<= 1) {
            int t = (tid >= off) ? sh[tid - off] : 0;
            __syncthreads();
            sh[tid] += t;
            __syncthreads();
        }
        if (i < NN) g_rowptr[i] = carry + sh[tid] - val;
        int tot = sh[1023];
        __syncthreads();
        if (tid == 0) carry += tot;
        __syncthreads();
    }
    if (tid == 0) g_rowptr[NN] = carry;
}
__global__ void k_scatter(const int* __restrict__ src, const int* __restrict__ dst) {
    int e = blockIdx.x * blockDim.x + threadIdx.x;
    if (e >= EE) return;
    int d = dst[e];
    int pos = atomicAdd(&g_fill[d], 1);
    g_csrc[g_rowptr[d] + pos] = src[e];
}

// ---------------- SAGE mean aggregation ----------------
__global__ void k_sage_agg(const float* __restrict__ x, float* __restrict__ mean) {
    int w = (blockIdx.x * blockDim.x + threadIdx.x) >> 5;
    int lane = threadIdx.x & 31;
    if (w >= NN) return;
    int beg = g_rowptr[w], end = g_rowptr[w + 1];
    float4 acc = make_float4(0.f, 0.f, 0.f, 0.f);
    for (int e = beg; e < end; e++) {
        int s = g_csrc[e];
        float4 xv = *(const float4*)(x + (size_t)s * 128 + lane * 4);
        acc.x += xv.x; acc.y += xv.y; acc.z += xv.z; acc.w += xv.w;
    }
    float inv = 1.0f / fmaxf((float)(end - beg), 1.0f);
    acc.x *= inv; acc.y *= inv; acc.z *= inv; acc.w *= inv;
    *(float4*)(mean + (size_t)w * 128 + lane * 4) = acc;
}

// ---------------- bf16x3 conversions ----------------
// A' = [Ahi | Ahi | Alo] per row; A logical = concat(s1[:K1], s2[:K-K1]) along K
__global__ void k_convA(const float* __restrict__ s1, int K1,
                        const float* __restrict__ s2, int K) {
    int idx = blockIdx.x * blockDim.x + threadIdx.x;
    if (idx >= MPAD * K) return;
    int m = idx / K;
    int k = idx - m * K;
    float val = 0.f;
    if (m < NN)
        val = (k < K1) ? s1[(size_t)m * K1 + k] : s2[(size_t)m * (K - K1) + (k - K1)];
    __nv_bfloat16 hi = __float2bfloat16(val);
    __nv_bfloat16 lo = __float2bfloat16(val - __bfloat162float(hi));
    __nv_bfloat16* row = g_Abf + (size_t)m * (3 * K);
    row[k] = hi;
    row[K + k] = hi;
    row[2 * K + k] = lo;
}

// W' rows (k-contig, transposed): [0,K)=hi, [K,2K)=lo, [2K,3K)=hi
// W logical = concat(W1[K1 rows], W2) along K, each [k][Nw] row-major.
__global__ void k_convW(const float* __restrict__ W1, int K1,
                        const float* __restrict__ W2, int K,
                        int Nw, int dstOff, int nSub) {
    // nSub: write n rows at dstOff + sub*Nw*3K (for fused qkvs images, nSub=1 normally)
    int idx = blockIdx.x * blockDim.x + threadIdx.x;
    if (idx >= Nw * K) return;
    int n = idx / K;
    int k = idx - n * K;
    float val = (k < K1) ? W1[(size_t)k * Nw + n] : W2[(size_t)(k - K1) * Nw + n];
    __nv_bfloat16 hi = __float2bfloat16(val);
    __nv_bfloat16 lo = __float2bfloat16(val - __bfloat162float(hi));
    __nv_bfloat16* row = g_Wbf + (size_t)dstOff + (size_t)n * (3 * K);
    row[k] = hi;
    row[K + k] = lo;
    row[2 * K + k] = hi;
    (void)nSub;
}

// ---------------- mma.sync bf16 GEMM ----------------
// C[M, Nc] = act(A' @ W'^T + bias); A' [MPAD][Ktot], W' [Nc][Ktot], Ktot % 64 == 0
// block 128x128, warp 64x32, k-tile 64
__global__ void __launch_bounds__(256, 2)
gemm_mma(const __nv_bfloat16* __restrict__ A, const __nv_bfloat16* __restrict__ W,
         const float* __restrict__ b0, const float* __restrict__ b1,
         const float* __restrict__ b2, const float* __restrict__ b3,
         float* __restrict__ C, int Nc, int Ktot, int act) {
    __shared__ __nv_bfloat16 sA[128 * 64];
    __shared__ __nv_bfloat16 sB[128 * 64];
    const int tid = threadIdx.x;
    const int wid = tid >> 5, lane = tid & 31;
    const int bm = blockIdx.y * 128;
    const int bn = blockIdx.x * 128;
    const int wm = (wid & 1) << 6;   // 0 or 64
    const int wn = (wid >> 1) << 5;  // 0,32,64,96

    float acc[4][4][4];
#pragma unroll
    for (int i = 0; i < 4; i++)
#pragma unroll
        for (int j = 0; j < 4; j++)
#pragma unroll
            for (int t = 0; t < 4; t++) acc[i][j][t] = 0.f;

    const uint32_t sAb = smem_u32(sA), sBb = smem_u32(sB);

    for (int k0 = 0; k0 < Ktot; k0 += 64) {
#pragma unroll
        for (int l = 0; l < 4; l++) {
            int idx = tid + l * 256;           // 0..1023
            int row = idx >> 3, u = idx & 7;   // row 0..127, 16B unit 0..7
            int sw = (u ^ (row & 7)) << 3;     // swizzled bf16 offset in row
            *(uint4*)(sA + row * 64 + sw) =
                *(const uint4*)(A + (size_t)(bm + row) * Ktot + k0 + u * 8);
            *(uint4*)(sB + row * 64 + sw) =
                *(const uint4*)(W + (size_t)(bn + row) * Ktot + k0 + u * 8);
        }
        __syncthreads();
#pragma unroll
        for (int s = 0; s < 4; s++) {
            uint32_t a[4][4], b[4][2];
#pragma unroll
            for (int i = 0; i < 4; i++) {
                int row = wm + i * 16 + (lane & 15);
                int u = (s << 1) + (lane >> 4);
                uint32_t ad = sAb + (uint32_t)(row * 64 + ((u ^ (row & 7)) << 3)) * 2;
                asm volatile("ldmatrix.sync.aligned.m8n8.x4.shared.b16 {%0,%1,%2,%3}, [%4];"
                    : "=r"(a[i][0]), "=r"(a[i][1]), "=r"(a[i][2]), "=r"(a[i][3]) : "r"(ad));
            }
#pragma unroll
            for (int jj = 0; jj < 2; jj++) {
                int row = wn + (jj << 4) + ((lane >> 4) << 3) + (lane & 7);
                int u = (s << 1) + ((lane >> 3) & 1);
                uint32_t ad = sBb + (uint32_t)(row * 64 + ((u ^ (row & 7)) << 3)) * 2;
                asm volatile("ldmatrix.sync.aligned.m8n8.x4.shared.b16 {%0,%1,%2,%3}, [%4];"
                    : "=r"(b[jj * 2][0]), "=r"(b[jj * 2][1]),
                      "=r"(b[jj * 2 + 1][0]), "=r"(b[jj * 2 + 1][1]) : "r"(ad));
            }
#pragma unroll
            for (int i = 0; i < 4; i++)
#pragma unroll
                for (int j = 0; j < 4; j++)
                    asm volatile("mma.sync.aligned.m16n8k16.row.col.f32.bf16.bf16.f32 "
                        "{%0,%1,%2,%3}, {%4,%5,%6,%7}, {%8,%9}, {%0,%1,%2,%3};"
                        : "+f"(acc[i][j][0]), "+f"(acc[i][j][1]),
                          "+f"(acc[i][j][2]), "+f"(acc[i][j][3])
                        : "r"(a[i][0]), "r"(a[i][1]), "r"(a[i][2]), "r"(a[i][3]),
                          "r"(b[j][0]), "r"(b[j][1]));
        }
        __syncthreads();
    }

    // epilogue: fused bias + activation
    const float* bsel[4] = {b0, b1, b2, b3};
#pragma unroll
    for (int i = 0; i < 4; i++) {
        int r0 = bm + wm + i * 16 + (lane >> 2);
        int r1 = r0 + 8;
#pragma unroll
        for (int j = 0; j < 4; j++) {
            int c = bn + wn + (j << 3) + ((lane & 3) << 1);
            const float* bp = bsel[c >> 8];
            float bv0 = bp[c & 255], bv1 = bp[(c & 255) + 1];
            float v00 = acc[i][j][0] + bv0, v01 = acc[i][j][1] + bv1;
            float v10 = acc[i][j][2] + bv0, v11 = acc[i][j][3] + bv1;
            if (act == 1) {
                v00 = fmaxf(v00, 0.f); v01 = fmaxf(v01, 0.f);
                v10 = fmaxf(v10, 0.f); v11 = fmaxf(v11, 0.f);
            } else if (act == 2) {
                v00 = 1.f / (1.f + __expf(-v00)); v01 = 1.f / (1.f + __expf(-v01));
                v10 = 1.f / (1.f + __expf(-v10)); v11 = 1.f / (1.f + __expf(-v11));
            }
            if (r0 < NN) { C[(size_t)r0 * Nc + c] = v00; C[(size_t)r0 * Nc + c + 1] = v01; }
            if (r1 < NN) { C[(size_t)r1 * Nc + c] = v10; C[(size_t)r1 * Nc + c + 1] = v11; }
        }
    }
}

// ---------------- attention: one warp per node, all 8 heads ----------------
// qkvs row [1024]: q[0,256) k[256,512) v[512,768) skip[768,1024)
// lane l owns cols l*4..l*4+3 of head l/8 (lo) and cols 128+l*4.. of head 4+l/8 (hi)
__global__ void k_attn(const float* __restrict__ qkvs, float* __restrict__ out) {
    int node = (blockIdx.x * blockDim.x + threadIdx.x) >> 5;
    if (node >= NN) return;
    int lane = threadIdx.x & 31;
    const float* base = qkvs + (size_t)node * 1024;
    float4 q0 = *(const float4*)(base + lane * 4);
    float4 q1 = *(const float4*)(base + 128 + lane * 4);
    int beg = g_rowptr[node], end = g_rowptr[node + 1];
    float m0 = -3.0e38f, s0 = 0.f, m1 = -3.0e38f, s1 = 0.f;
    float4 a0 = make_float4(0.f, 0.f, 0.f, 0.f);
    float4 a1 = make_float4(0.f, 0.f, 0.f, 0.f);
    const float scl = 0.17677669529663687f;  // 1/sqrt(32)
    for (int e = beg; e < end; e++) {
        int sn = g_csrc[e];
        const float* kb = qkvs + (size_t)sn * 1024 + 256;
        float4 k0 = *(const float4*)(kb + lane * 4);
        float4 k1 = *(const float4*)(kb + 128 + lane * 4);
        float4 v0 = *(const float4*)(kb + 256 + lane * 4);
        float4 v1 = *(const float4*)(kb + 384 + lane * 4);
        float d0 = q0.x * k0.x + q0.y * k0.y + q0.z * k0.z + q0.w * k0.w;
        float d1 = q1.x * k1.x + q1.y * k1.y + q1.z * k1.z + q1.w * k1.w;
#pragma unroll
        for (int off = 4; off; off >>= 1) {
            d0 += __shfl_xor_sync(0xffffffffu, d0, off);
            d1 += __shfl_xor_sync(0xffffffffu, d1, off);
        }
        d0 *= scl; d1 *= scl;
        float mn0 = fmaxf(m0, d0);
        float sc0 = __expf(m0 - mn0);
        float p0 = __expf(d0 - mn0);
        s0 = s0 * sc0 + p0;
        a0.x = a0.x * sc0 + p0 * v0.x; a0.y = a0.y * sc0 + p0 * v0.y;
        a0.z = a0.z * sc0 + p0 * v0.z; a0.w = a0.w * sc0 + p0 * v0.w;
        m0 = mn0;
        float mn1 = fmaxf(m1, d1);
        float sc1 = __expf(m1 - mn1);
        float p1 = __expf(d1 - mn1);
        s1 = s1 * sc1 + p1;
        a1.x = a1.x * sc1 + p1 * v1.x; a1.y = a1.y * sc1 + p1 * v1.y;
        a1.z = a1.z * sc1 + p1 * v1.z; a1.w = a1.w * sc1 + p1 * v1.w;
        m1 = mn1;
    }
    float inv0 = (end > beg) ? (1.f / s0) : 0.f;
    float inv1 = (end > beg) ? (1.f / s1) : 0.f;
    const float* sk = base + 768;
    float4 sk0 = *(const float4*)(sk + lane * 4);
    float4 sk1 = *(const float4*)(sk + 128 + lane * 4);
    float4 o0, o1;
    o0.x = fmaxf(sk0.x + a0.x * inv0, 0.f); o0.y = fmaxf(sk0.y + a0.y * inv0, 0.f);
    o0.z = fmaxf(sk0.z + a0.z * inv0, 0.f); o0.w = fmaxf(sk0.w + a0.w * inv0, 0.f);
    o1.x = fmaxf(sk1.x + a1.x * inv1, 0.f); o1.y = fmaxf(sk1.y + a1.y * inv1, 0.f);
    o1.z = fmaxf(sk1.z + a1.z * inv1, 0.f); o1.w = fmaxf(sk1.w + a1.w * inv1, 0.f);
    *(float4*)(out + (size_t)node * 256 + lane * 4) = o0;
    *(float4*)(out + (size_t)node * 256 + 128 + lane * 4) = o1;
}

// ---------------- global max pool ----------------
__global__ void k_pool(const int* __restrict__ batch, float* __restrict__ out) {
    int i = blockIdx.x * blockDim.x + threadIdx.x;
    if (i >= NN * 128) return;
    int node = i >> 7;
    int d = i & 127;
    float val = g_p2[i];
    atomicMax((int*)&out[(size_t)batch[node] * 128 + d], __float_as_int(val));
}

// ---------------- host orchestration ----------------
static void run_gemm(const __nv_bfloat16* A, const __nv_bfloat16* W,
                     const float* b0, const float* b1, const float* b2, const float* b3,
                     float* C, int Nc, int Ktot, int act) {
    dim3 grid(Nc / 128, NTILES);
    gemm_mma<<<grid, 256>>>(A, W, b0, b1, b2, b3, C, Nc, Ktot, act);
}

extern "C" void kernel_launch(void* const* d_in, const int* in_sizes, int n_in,
                              void* d_out, int out_size) {
    const float* x     = (const float*)d_in[0];
    const int*   ei    = (const int*)d_in[1];
    const int*   batch = (const int*)d_in[2];
    const float* s1_wl = (const float*)d_in[3];
    const float* s1_bl = (const float*)d_in[4];
    const float* s1_wr = (const float*)d_in[5];
    const float* s2_wl = (const float*)d_in[6];
    const float* s2_bl = (const float*)d_in[7];
    const float* s2_wr = (const float*)d_in[8];
    const float* t1_wq = (const float*)d_in[9];
    const float* t1_bq = (const float*)d_in[10];
    const float* t1_wk = (const float*)d_in[11];
    const float* t1_bk = (const float*)d_in[12];
    const float* t1_wv = (const float*)d_in[13];
    const float* t1_bv = (const float*)d_in[14];
    const float* t1_ws = (const float*)d_in[15];
    const float* t1_bs = (const float*)d_in[16];
    const float* t2_wq = (const float*)d_in[17];
    const float* t2_bq = (const float*)d_in[18];
    const float* t2_wk = (const float*)d_in[19];
    const float* t2_bk = (const float*)d_in[20];
    const float* t2_wv = (const float*)d_in[21];
    const float* t2_bv = (const float*)d_in[22];
    const float* t2_ws = (const float*)d_in[23];
    const float* t2_bs = (const float*)d_in[24];
    const float* p1_w  = (const float*)d_in[25];
    const float* p1_b  = (const float*)d_in[26];
    const float* p2_w  = (const float*)d_in[27];
    const float* p2_b  = (const float*)d_in[28];

    const int* e_src = ei;
    const int* e_dst = ei + EE;

    float *d_mean, *d_h1, *d_h2, *d_h3, *d_h4, *d_qkvs, *d_p1, *d_p2;
    __nv_bfloat16 *d_A, *d_W;
    cudaGetSymbolAddress((void**)&d_mean, g_mean);
    cudaGetSymbolAddress((void**)&d_h1, g_h1);
    cudaGetSymbolAddress((void**)&d_h2, g_h2);
    cudaGetSymbolAddress((void**)&d_h3, g_h3);
    cudaGetSymbolAddress((void**)&d_h4, g_h4);
    cudaGetSymbolAddress((void**)&d_qkvs, g_qkvs);
    cudaGetSymbolAddress((void**)&d_p1, g_p1);
    cudaGetSymbolAddress((void**)&d_p2, g_p2);
    cudaGetSymbolAddress((void**)&d_A, g_Abf);
    cudaGetSymbolAddress((void**)&d_W, g_Wbf);

    // CSR build
    k_zero<<<(NN + 255) / 256, 256>>>((float*)d_out);
    k_hist<<<(EE + 255) / 256, 256>>>(e_dst);
    k_scan<<<1, 1024>>>();
    k_scatter<<<(EE + 255) / 256, 256>>>(e_src, e_dst);

    // weight images
#define CONVW(W1, K1, W2, K, NW, OFF) \
    k_convW<<<((NW) * (K) + 255) / 256, 256>>>(W1, K1, W2, K, NW, OFF, 1)
    CONVW(s1_wl, 128, s1_wr, 256, 128, OFF_S1);
    CONVW(s2_wl, 128, s2_wr, 256, 256, OFF_S2);
    CONVW(t1_wq, 256, t1_wq, 256, 256, OFF_T1 + 0 * 256 * 768);
    CONVW(t1_wk, 256, t1_wk, 256, 256, OFF_T1 + 1 * 256 * 768);
    CONVW(t1_wv, 256, t1_wv, 256, 256, OFF_T1 + 2 * 256 * 768);
    CONVW(t1_ws, 256, t1_ws, 256, 256, OFF_T1 + 3 * 256 * 768);
    CONVW(t2_wq, 256, t2_wq, 256, 256, OFF_T2 + 0 * 256 * 768);
    CONVW(t2_wk, 256, t2_wk, 256, 256, OFF_T2 + 1 * 256 * 768);
    CONVW(t2_wv, 256, t2_wv, 256, 256, OFF_T2 + 2 * 256 * 768);
    CONVW(t2_ws, 256, t2_ws, 256, 256, OFF_T2 + 3 * 256 * 768);
    CONVW(p1_w, 256, p1_w, 256, 512, OFF_P1);
    CONVW(p2_w, 512, p2_w, 512, 128, OFF_P2);

#define CONVA(S1, K1, S2, K) \
    k_convA<<<(MPAD * (K) + 255) / 256, 256>>>(S1, K1, S2, K)

    // SAGE 1: h1 = relu([mean(x)|x] @ [wl;wr] + bl)  [N,128]
    k_sage_agg<<<(NN * 32 + 255) / 256, 256>>>(x, d_mean);
    CONVA(d_mean, 128, x, 256);
    run_gemm(d_A, d_W + OFF_S1, s1_bl, s1_bl, s1_bl, s1_bl, d_h1, 128, 768, 1);

    // SAGE 2 -> h2 [N,256]
    k_sage_agg<<<(NN * 32 + 255) / 256, 256>>>(d_h1, d_mean);
    CONVA(d_mean, 128, d_h1, 256);
    run_gemm(d_A, d_W + OFF_S2, s2_bl, s2_bl, s2_bl, s2_bl, d_h2, 256, 768, 1);

    // TransformerConv 1: fused q|k|v|skip projection [N,1024], then attention
    CONVA(d_h2, 256, d_h2, 256);
    run_gemm(d_A, d_W + OFF_T1, t1_bq, t1_bk, t1_bv, t1_bs, d_qkvs, 1024, 768, 0);
    k_attn<<<(NN * 32 + 255) / 256, 256>>>(d_qkvs, d_h3);

    // TransformerConv 2
    CONVA(d_h3, 256, d_h3, 256);
    run_gemm(d_A, d_W + OFF_T2, t2_bq, t2_bk, t2_bv, t2_bs, d_qkvs, 1024, 768, 0);
    k_attn<<<(NN * 32 + 255) / 256, 256>>>(d_qkvs, d_h4);

    // proj MLP
    CONVA(d_h4, 256, d_h4, 256);
    run_gemm(d_A, d_W + OFF_P1, p1_b, p1_b + 256, p1_b, p1_b, d_p1, 512, 768, 1);
    CONVA(d_p1, 512, d_p1, 512);
    run_gemm(d_A, d_W + OFF_P2, p2_b, p2_b, p2_b, p2_b, d_p2, 128, 1536, 2);

    // global max pool per graph
    k_pool<<<(NN * 128 + 255) / 256, 256>>>(batch, (float*)d_out);
}

// round 4
// speedup vs baseline: 2.7109x; 1.3700x over previous
#include <cuda_runtime.h>
#include <cuda_bf16.h>
#include <math.h>
#include <stdint.h>

#define NN 20000
#define EE 320000
#define GG 64
#define MPAD 20096          // 157 * 128
#define NTILES 157

// ---------------- device scratch ----------------
__device__ float g_h1[NN * 128];
__device__ float g_qkvs[(size_t)NN * 1024];
__device__ int g_deg[NN];
__device__ int g_fill[NN];
__device__ int g_rowptr[NN + 1];
__device__ int g_csrc[EE];

// ping-pong bf16x3 A-images: [MPAD][3K], widest K=512 -> 1536 cols
__device__ __nv_bfloat16 g_img0[(size_t)MPAD * 1536];
__device__ __nv_bfloat16 g_img1[(size_t)MPAD * 1536];
__device__ __nv_bfloat16 g_Wbf[2457600];

// weight image offsets (elements), layout [Nc][3K]
#define OFF_S1   0
#define OFF_S2   98304
#define OFF_T1   294912
#define OFF_T2   1081344
#define OFF_P1   1867776
#define OFF_P2   2260992

__device__ __forceinline__ uint32_t smem_u32(const void* p) {
    uint32_t a;
    asm("{ .reg .u64 t; cvta.to.shared.u64 t, %1; cvt.u32.u64 %0, t; }" : "=r"(a) : "l"(p));
    return a;
}
__device__ __forceinline__ void cpa16(uint32_t dst, const void* src) {
    asm volatile("cp.async.cg.shared.global [%0], [%1], 16;" :: "r"(dst), "l"(src));
}

// write 4 consecutive floats as hi|hi|lo into image row (imgK=256 layout)
__device__ __forceinline__ void img_write4(__nv_bfloat16* row, int c, float4 v) {
    __nv_bfloat162 hh0, hh1, ll0, ll1;
    hh0.x = __float2bfloat16(v.x); hh0.y = __float2bfloat16(v.y);
    hh1.x = __float2bfloat16(v.z); hh1.y = __float2bfloat16(v.w);
    ll0.x = __float2bfloat16(v.x - __bfloat162float(hh0.x));
    ll0.y = __float2bfloat16(v.y - __bfloat162float(hh0.y));
    ll1.x = __float2bfloat16(v.z - __bfloat162float(hh1.x));
    ll1.y = __float2bfloat16(v.w - __bfloat162float(hh1.y));
    *(__nv_bfloat162*)(row + c) = hh0;       *(__nv_bfloat162*)(row + c + 2) = hh1;
    *(__nv_bfloat162*)(row + 256 + c) = hh0; *(__nv_bfloat162*)(row + 256 + c + 2) = hh1;
    *(__nv_bfloat162*)(row + 512 + c) = ll0; *(__nv_bfloat162*)(row + 512 + c + 2) = ll1;
}

// ---------------- CSR build ----------------
__global__ void k_zero(float* out) {
    int i = blockIdx.x * blockDim.x + threadIdx.x;
    if (i < NN) { g_deg[i] = 0; g_fill[i] = 0; }
    if (i < GG * 128) out[i] = 0.0f;
}
__global__ void k_hist(const int* __restrict__ dst) {
    int e = blockIdx.x * blockDim.x + threadIdx.x;
    if (e < EE) atomicAdd(&g_deg[dst[e]], 1);
}
__global__ void k_scan() {
    __shared__ int sh[1024];
    __shared__ int carry;
    int tid = threadIdx.x;
    if (tid == 0) carry = 0;
    __syncthreads();
    for (int base = 0; base < NN; base += 1024) {
        int i = base + tid;
        int val = (i < NN) ? g_deg[i] : 0;
        sh[tid] = val;
        __syncthreads();
        for (int off = 1; off < 1024; off <<= 1) {
            int t = (tid >= off) ? sh[tid - off] : 0;
            __syncthreads();
            sh[tid] += t;
            __syncthreads();
        }
        if (i < NN) g_rowptr[i] = carry + sh[tid] - val;
        int tot = sh[1023];
        __syncthreads();
        if (tid == 0) carry += tot;
        __syncthreads();
    }
    if (tid == 0) g_rowptr[NN] = carry;
}
__global__ void k_scatter(const int* __restrict__ src, const int* __restrict__ dst) {
    int e = blockIdx.x * blockDim.x + threadIdx.x;
    if (e >= EE) return;
    int d = dst[e];
    int pos = atomicAdd(&g_fill[d], 1);
    g_csrc[g_rowptr[d] + pos] = src[e];
}

// ---------------- SAGE mean aggregation -> image cols [0,128) ----------------
__global__ void k_sage_agg(const float* __restrict__ x, __nv_bfloat16* __restrict__ img) {
    int w = (blockIdx.x * blockDim.x + threadIdx.x) >> 5;
    int lane = threadIdx.x & 31;
    if (w >= NN) return;
    int beg = g_rowptr[w], end = g_rowptr[w + 1];
    float4 acc = make_float4(0.f, 0.f, 0.f, 0.f);
    for (int e = beg; e < end; e++) {
        int s = g_csrc[e];
        float4 xv = *(const float4*)(x + (size_t)s * 128 + lane * 4);
        acc.x += xv.x; acc.y += xv.y; acc.z += xv.z; acc.w += xv.w;
    }
    float inv = 1.0f / fmaxf((float)(end - beg), 1.0f);
    acc.x *= inv; acc.y *= inv; acc.z *= inv; acc.w *= inv;
    img_write4(img + (size_t)w * 768, lane * 4, acc);
}

// ---------------- x -> image cols [128,256) ----------------
__global__ void k_convX(const float* __restrict__ x, __nv_bfloat16* __restrict__ img) {
    int idx = blockIdx.x * blockDim.x + threadIdx.x;
    if (idx >= NN * 32) return;
    int m = idx >> 5;
    int k = (idx & 31) * 4;
    float4 v = *(const float4*)(x + (size_t)m * 128 + k);
    img_write4(img + (size_t)m * 768, 128 + k, v);
}

// ---------------- weight conversion: [Nc][3K] = hi|lo|hi ----------------
__global__ void k_convW(const float* __restrict__ W1, int K1,
                        const float* __restrict__ W2, int K,
                        int Nw, int dstOff) {
    int idx = blockIdx.x * blockDim.x + threadIdx.x;
    if (idx >= Nw * K) return;
    int n = idx / K;
    int k = idx - n * K;
    float val = (k < K1) ? W1[(size_t)k * Nw + n] : W2[(size_t)(k - K1) * Nw + n];
    __nv_bfloat16 hi = __float2bfloat16(val);
    __nv_bfloat16 lo = __float2bfloat16(val - __bfloat162float(hi));
    __nv_bfloat16* row = g_Wbf + (size_t)dstOff + (size_t)n * (3 * K);
    row[k] = hi;
    row[K + k] = lo;
    row[2 * K + k] = hi;
}

// ---------------- pipelined mma.sync bf16 GEMM ----------------
// C = act(A' @ W'^T + bias), 128x128 block, 64 k-tile, cp.async 2-stage
#define STAGE_BYTES 32768

__global__ void __launch_bounds__(256, 2)
gemm_mma(const __nv_bfloat16* __restrict__ A, const __nv_bfloat16* __restrict__ W,
         const float* __restrict__ b0, const float* __restrict__ b1,
         const float* __restrict__ b2, const float* __restrict__ b3,
         float* __restrict__ C, int Nc, int Ktot, int act,
         __nv_bfloat16* __restrict__ img, int imgK, int imgColOff,
         const int* __restrict__ batch, float* __restrict__ pool) {
    extern __shared__ char smem[];
    const int tid = threadIdx.x;
    const int wid = tid >> 5, lane = tid & 31;
    const int bm = blockIdx.y * 128;
    const int bn = blockIdx.x * 128;
    const int wm = (wid & 1) << 6;
    const int wn = (wid >> 1) << 5;
    const uint32_t sb = smem_u32(smem);

    float acc[4][4][4];
#pragma unroll
    for (int i = 0; i < 4; i++)
#pragma unroll
        for (int j = 0; j < 4; j++)
#pragma unroll
            for (int t = 0; t < 4; t++) acc[i][j][t] = 0.f;

    const int nK = Ktot >> 6;

    // issue stage c into buffer buf
#define ISSUE(c, buf) do { \
        int _k0 = (c) << 6; \
        uint32_t _base = sb + (buf) * STAGE_BYTES; \
        _Pragma("unroll") \
        for (int l = 0; l < 4; l++) { \
            int idx = tid + l * 256; \
            int row = idx >> 3, u = idx & 7; \
            uint32_t sw = row * 128 + ((u ^ (row & 7)) << 4); \
            cpa16(_base + sw, A + (size_t)(bm + row) * Ktot + _k0 + u * 8); \
            cpa16(_base + 16384 + sw, W + (size_t)(bn + row) * Ktot + _k0 + u * 8); \
        } \
        asm volatile("cp.async.commit_group;" ::: "memory"); \
    } while (0)

    ISSUE(0, 0);
    for (int c = 0; c < nK; c++) {
        int buf = c & 1;
        if (c + 1 < nK) {
            ISSUE(c + 1, (c + 1) & 1);
            asm volatile("cp.async.wait_group 1;" ::: "memory");
        } else {
            asm volatile("cp.async.wait_group 0;" ::: "memory");
        }
        __syncthreads();

        uint32_t sAb = sb + buf * STAGE_BYTES;
        uint32_t sBb = sAb + 16384;
#pragma unroll
        for (int s = 0; s < 4; s++) {
            uint32_t a[4][4], b[4][2];
#pragma unroll
            for (int i = 0; i < 4; i++) {
                int row = wm + i * 16 + (lane & 15);
                int u = (s << 1) + (lane >> 4);
                uint32_t ad = sAb + row * 128 + ((u ^ (row & 7)) << 4);
                asm volatile("ldmatrix.sync.aligned.m8n8.x4.shared.b16 {%0,%1,%2,%3}, [%4];"
                    : "=r"(a[i][0]), "=r"(a[i][1]), "=r"(a[i][2]), "=r"(a[i][3]) : "r"(ad));
            }
#pragma unroll
            for (int jj = 0; jj < 2; jj++) {
                int row = wn + (jj << 4) + ((lane >> 4) << 3) + (lane & 7);
                int u = (s << 1) + ((lane >> 3) & 1);
                uint32_t ad = sBb + row * 128 + ((u ^ (row & 7)) << 4);
                asm volatile("ldmatrix.sync.aligned.m8n8.x4.shared.b16 {%0,%1,%2,%3}, [%4];"
                    : "=r"(b[jj * 2][0]), "=r"(b[jj * 2][1]),
                      "=r"(b[jj * 2 + 1][0]), "=r"(b[jj * 2 + 1][1]) : "r"(ad));
            }
#pragma unroll
            for (int i = 0; i < 4; i++)
#pragma unroll
                for (int j = 0; j < 4; j++)
                    asm volatile("mma.sync.aligned.m16n8k16.row.col.f32.bf16.bf16.f32 "
                        "{%0,%1,%2,%3}, {%4,%5,%6,%7}, {%8,%9}, {%0,%1,%2,%3};"
                        : "+f"(acc[i][j][0]), "+f"(acc[i][j][1]),
                          "+f"(acc[i][j][2]), "+f"(acc[i][j][3])
                        : "r"(a[i][0]), "r"(a[i][1]), "r"(a[i][2]), "r"(a[i][3]),
                          "r"(b[j][0]), "r"(b[j][1]));
        }
        __syncthreads();
    }

    // epilogue
    const float* bsel[4] = {b0, b1, b2, b3};
    const int stride3K = 3 * imgK;
#pragma unroll
    for (int i = 0; i < 4; i++) {
        int r0 = bm + wm + i * 16 + (lane >> 2);
        int r1 = r0 + 8;
#pragma unroll
        for (int j = 0; j < 4; j++) {
            int c = bn + wn + (j << 3) + ((lane & 3) << 1);
            const float* bp = bsel[c >> 8];
            float bv0 = bp[c & 255], bv1 = bp[(c & 255) + 1];
            float v00 = acc[i][j][0] + bv0, v01 = acc[i][j][1] + bv1;
            float v10 = acc[i][j][2] + bv0, v11 = acc[i][j][3] + bv1;
            if (act == 1) {
                v00 = fmaxf(v00, 0.f); v01 = fmaxf(v01, 0.f);
                v10 = fmaxf(v10, 0.f); v11 = fmaxf(v11, 0.f);
            } else if (act == 2) {
                v00 = 1.f / (1.f + __expf(-v00)); v01 = 1.f / (1.f + __expf(-v01));
                v10 = 1.f / (1.f + __expf(-v10)); v11 = 1.f / (1.f + __expf(-v11));
            }
            if (C) {
                if (r0 < NN) { C[(size_t)r0 * Nc + c] = v00; C[(size_t)r0 * Nc + c + 1] = v01; }
                if (r1 < NN) { C[(size_t)r1 * Nc + c] = v10; C[(size_t)r1 * Nc + c + 1] = v11; }
            }
            if (img) {
                int ic = imgColOff + c;
                if (r0 < NN) {
                    __nv_bfloat16* row = img + (size_t)r0 * stride3K;
                    __nv_bfloat162 hh, ll;
                    hh.x = __float2bfloat16(v00); hh.y = __float2bfloat16(v01);
                    ll.x = __float2bfloat16(v00 - __bfloat162float(hh.x));
                    ll.y = __float2bfloat16(v01 - __bfloat162float(hh.y));
                    *(__nv_bfloat162*)(row + ic) = hh;
                    *(__nv_bfloat162*)(row + imgK + ic) = hh;
                    *(__nv_bfloat162*)(row + 2 * imgK + ic) = ll;
                }
                if (r1 < NN) {
                    __nv_bfloat16* row = img + (size_t)r1 * stride3K;
                    __nv_bfloat162 hh, ll;
                    hh.x = __float2bfloat16(v10); hh.y = __float2bfloat16(v11);
                    ll.x = __float2bfloat16(v10 - __bfloat162float(hh.x));
                    ll.y = __float2bfloat16(v11 - __bfloat162float(hh.y));
                    *(__nv_bfloat162*)(row + ic) = hh;
                    *(__nv_bfloat162*)(row + imgK + ic) = hh;
                    *(__nv_bfloat162*)(row + 2 * imgK + ic) = ll;
                }
            }
            if (pool) {
                if (r0 < NN) {
                    int g = batch[r0] * 128;
                    atomicMax((int*)&pool[g + c], __float_as_int(v00));
                    atomicMax((int*)&pool[g + c + 1], __float_as_int(v01));
                }
                if (r1 < NN) {
                    int g = batch[r1] * 128;
                    atomicMax((int*)&pool[g + c], __float_as_int(v10));
                    atomicMax((int*)&pool[g + c + 1], __float_as_int(v11));
                }
            }
        }
    }
}

// ---------------- attention: warp per node, 8 heads; writes image ----------
__global__ void k_attn(const float* __restrict__ qkvs, __nv_bfloat16* __restrict__ img) {
    int node = (blockIdx.x * blockDim.x + threadIdx.x) >> 5;
    if (node >= NN) return;
    int lane = threadIdx.x & 31;
    const float* base = qkvs + (size_t)node * 1024;
    float4 q0 = *(const float4*)(base + lane * 4);
    float4 q1 = *(const float4*)(base + 128 + lane * 4);
    int beg = g_rowptr[node], end = g_rowptr[node + 1];
    float m0 = -3.0e38f, s0 = 0.f, m1 = -3.0e38f, s1 = 0.f;
    float4 a0 = make_float4(0.f, 0.f, 0.f, 0.f);
    float4 a1 = make_float4(0.f, 0.f, 0.f, 0.f);
    const float scl = 0.17677669529663687f;
    for (int e = beg; e < end; e++) {
        int sn = g_csrc[e];
        const float* kb = qkvs + (size_t)sn * 1024 + 256;
        float4 k0 = *(const float4*)(kb + lane * 4);
        float4 k1 = *(const float4*)(kb + 128 + lane * 4);
        float4 v0 = *(const float4*)(kb + 256 + lane * 4);
        float4 v1 = *(const float4*)(kb + 384 + lane * 4);
        float d0 = q0.x * k0.x + q0.y * k0.y + q0.z * k0.z + q0.w * k0.w;
        float d1 = q1.x * k1.x + q1.y * k1.y + q1.z * k1.z + q1.w * k1.w;
#pragma unroll
        for (int off = 4; off; off >>= 1) {
            d0 += __shfl_xor_sync(0xffffffffu, d0, off);
            d1 += __shfl_xor_sync(0xffffffffu, d1, off);
        }
        d0 *= scl; d1 *= scl;
        float mn0 = fmaxf(m0, d0);
        float sc0 = __expf(m0 - mn0);
        float p0 = __expf(d0 - mn0);
        s0 = s0 * sc0 + p0;
        a0.x = a0.x * sc0 + p0 * v0.x; a0.y = a0.y * sc0 + p0 * v0.y;
        a0.z = a0.z * sc0 + p0 * v0.z; a0.w = a0.w * sc0 + p0 * v0.w;
        m0 = mn0;
        float mn1 = fmaxf(m1, d1);
        float sc1 = __expf(m1 - mn1);
        float p1 = __expf(d1 - mn1);
        s1 = s1 * sc1 + p1;
        a1.x = a1.x * sc1 + p1 * v1.x; a1.y = a1.y * sc1 + p1 * v1.y;
        a1.z = a1.z * sc1 + p1 * v1.z; a1.w = a1.w * sc1 + p1 * v1.w;
        m1 = mn1;
    }
    float inv0 = (end > beg) ? (1.f / s0) : 0.f;
    float inv1 = (end > beg) ? (1.f / s1) : 0.f;
    const float* sk = base + 768;
    float4 sk0 = *(const float4*)(sk + lane * 4);
    float4 sk1 = *(const float4*)(sk + 128 + lane * 4);
    float4 o0, o1;
    o0.x = fmaxf(sk0.x + a0.x * inv0, 0.f); o0.y = fmaxf(sk0.y + a0.y * inv0, 0.f);
    o0.z = fmaxf(sk0.z + a0.z * inv0, 0.f); o0.w = fmaxf(sk0.w + a0.w * inv0, 0.f);
    o1.x = fmaxf(sk1.x + a1.x * inv1, 0.f); o1.y = fmaxf(sk1.y + a1.y * inv1, 0.f);
    o1.z = fmaxf(sk1.z + a1.z * inv1, 0.f); o1.w = fmaxf(sk1.w + a1.w * inv1, 0.f);
    __nv_bfloat16* row = img + (size_t)node * 768;
    img_write4(row, lane * 4, o0);
    img_write4(row, 128 + lane * 4, o1);
}

// ---------------- host orchestration ----------------
static void run_gemm(const __nv_bfloat16* A, const __nv_bfloat16* W,
                     const float* b0, const float* b1, const float* b2, const float* b3,
                     float* C, int Nc, int Ktot, int act,
                     __nv_bfloat16* img, int imgK, int imgColOff,
                     const int* batch, float* pool) {
    dim3 grid(Nc / 128, NTILES);
    gemm_mma<<<grid, 256, 2 * STAGE_BYTES>>>(A, W, b0, b1, b2, b3, C, Nc, Ktot, act,
                                             img, imgK, imgColOff, batch, pool);
}

extern "C" void kernel_launch(void* const* d_in, const int* in_sizes, int n_in,
                              void* d_out, int out_size) {
    const float* x     = (const float*)d_in[0];
    const int*   ei    = (const int*)d_in[1];
    const int*   batch = (const int*)d_in[2];
    const float* s1_wl = (const float*)d_in[3];
    const float* s1_bl = (const float*)d_in[4];
    const float* s1_wr = (const float*)d_in[5];
    const float* s2_wl = (const float*)d_in[6];
    const float* s2_bl = (const float*)d_in[7];
    const float* s2_wr = (const float*)d_in[8];
    const float* t1_wq = (const float*)d_in[9];
    const float* t1_bq = (const float*)d_in[10];
    const float* t1_wk = (const float*)d_in[11];
    const float* t1_bk = (const float*)d_in[12];
    const float* t1_wv = (const float*)d_in[13];
    const float* t1_bv = (const float*)d_in[14];
    const float* t1_ws = (const float*)d_in[15];
    const float* t1_bs = (const float*)d_in[16];
    const float* t2_wq = (const float*)d_in[17];
    const float* t2_bq = (const float*)d_in[18];
    const float* t2_wk = (const float*)d_in[19];
    const float* t2_bk = (const float*)d_in[20];
    const float* t2_wv = (const float*)d_in[21];
    const float* t2_bv = (const float*)d_in[22];
    const float* t2_ws = (const float*)d_in[23];
    const float* t2_bs = (const float*)d_in[24];
    const float* p1_w  = (const float*)d_in[25];
    const float* p1_b  = (const float*)d_in[26];
    const float* p2_w  = (const float*)d_in[27];
    const float* p2_b  = (const float*)d_in[28];

    const int* e_src = ei;
    const int* e_dst = ei + EE;

    cudaFuncSetAttribute(gemm_mma, cudaFuncAttributeMaxDynamicSharedMemorySize,
                         2 * STAGE_BYTES);

    float *d_h1, *d_qkvs;
    __nv_bfloat16 *d_i0, *d_i1, *d_W;
    cudaGetSymbolAddress((void**)&d_h1, g_h1);
    cudaGetSymbolAddress((void**)&d_qkvs, g_qkvs);
    cudaGetSymbolAddress((void**)&d_i0, g_img0);
    cudaGetSymbolAddress((void**)&d_i1, g_img1);
    cudaGetSymbolAddress((void**)&d_W, g_Wbf);

    // CSR build
    k_zero<<<(NN + 255) / 256, 256>>>((float*)d_out);
    k_hist<<<(EE + 255) / 256, 256>>>(e_dst);
    k_scan<<<1, 1024>>>();
    k_scatter<<<(EE + 255) / 256, 256>>>(e_src, e_dst);

    // weight images
#define CONVW(W1, K1, W2, K, NW, OFF) \
    k_convW<<<((NW) * (K) + 255) / 256, 256>>>(W1, K1, W2, K, NW, OFF)
    CONVW(s1_wl, 128, s1_wr, 256, 128, OFF_S1);
    CONVW(s2_wl, 128, s2_wr, 256, 256, OFF_S2);
    CONVW(t1_wq, 256, t1_wq, 256, 256, OFF_T1 + 0 * 256 * 768);
    CONVW(t1_wk, 256, t1_wk, 256, 256, OFF_T1 + 1 * 256 * 768);
    CONVW(t1_wv, 256, t1_wv, 256, 256, OFF_T1 + 2 * 256 * 768);
    CONVW(t1_ws, 256, t1_ws, 256, 256, OFF_T1 + 3 * 256 * 768);
    CONVW(t2_wq, 256, t2_wq, 256, 256, OFF_T2 + 0 * 256 * 768);
    CONVW(t2_wk, 256, t2_wk, 256, 256, OFF_T2 + 1 * 256 * 768);
    CONVW(t2_wv, 256, t2_wv, 256, 256, OFF_T2 + 2 * 256 * 768);
    CONVW(t2_ws, 256, t2_ws, 256, 256, OFF_T2 + 3 * 256 * 768);
    CONVW(p1_w, 256, p1_w, 256, 512, OFF_P1);
    CONVW(p2_w, 512, p2_w, 512, 128, OFF_P2);

    // SAGE 1 input image (img0): mean(x) cols [0,128), x cols [128,256)
    k_convX<<<(NN * 32 + 255) / 256, 256>>>(x, d_i0);
    k_sage_agg<<<(NN * 32 + 255) / 256, 256>>>(x, d_i0);
    // S1: h1 fp32 + img1[128:256)
    run_gemm(d_i0, d_W + OFF_S1, s1_bl, s1_bl, s1_bl, s1_bl,
             d_h1, 128, 768, 1, d_i1, 256, 128, nullptr, nullptr);

    // SAGE 2: mean(h1) -> img1[0:128); S2 -> img0[0:256)
    k_sage_agg<<<(NN * 32 + 255) / 256, 256>>>(d_h1, d_i1);
    run_gemm(d_i1, d_W + OFF_S2, s2_bl, s2_bl, s2_bl, s2_bl,
             nullptr, 256, 768, 1, d_i0, 256, 0, nullptr, nullptr);

    // TransformerConv 1
    run_gemm(d_i0, d_W + OFF_T1, t1_bq, t1_bk, t1_bv, t1_bs,
             d_qkvs, 1024, 768, 0, nullptr, 0, 0, nullptr, nullptr);
    k_attn<<<(NN * 32 + 255) / 256, 256>>>(d_qkvs, d_i1);

    // TransformerConv 2
    run_gemm(d_i1, d_W + OFF_T2, t2_bq, t2_bk, t2_bv, t2_bs,
             d_qkvs, 1024, 768, 0, nullptr, 0, 0, nullptr, nullptr);
    k_attn<<<(NN * 32 + 255) / 256, 256>>>(d_qkvs, d_i0);

    // proj MLP: P1 -> img1 (K=512); P2 -> sigmoid + fused pool
    run_gemm(d_i0, d_W + OFF_P1, p1_b, p1_b + 256, p1_b, p1_b,
             nullptr, 512, 768, 1, d_i1, 512, 0, nullptr, nullptr);
    run_gemm(d_i1, d_W + OFF_P2, p2_b, p2_b, p2_b, p2_b,
             nullptr, 128, 1536, 2, nullptr, 0, 0, batch, (float*)d_out);
}